// round 4
// baseline (speedup 1.0000x reference)
#include <cuda_runtime.h>
#include <cuda_bf16.h>
#include <stdint.h>

// GatherRouter combine: out[tag[i]] += data[i] over 65536 rows of 1024 fp32,
// into 16384 slots. Strategy: counting-sort rows by tag, then one block per
// output slot does a plain (non-atomic) coalesced reduction.
//
// NOTE: tags are int32 (JAX without x64 downgrades requested int64 -> int32).

#define E_TOT   8
#define N_TOK   8192
#define NROWS   (E_TOT * N_TOK)      // 65536
#define DDIM    1024
#define NSLOTS  16384

// Scratch (no allocations allowed): small metadata arrays.
__device__ int g_counts[NSLOTS];
__device__ int g_cursor[NSLOTS];
__device__ int g_offsets[NSLOTS];
__device__ int g_rows[NROWS];

// ---------------------------------------------------------------------------
// K0: zero counters
__global__ void k_init() {
    int i = blockIdx.x * blockDim.x + threadIdx.x;
    if (i < NSLOTS) {
        g_counts[i] = 0;
        g_cursor[i] = 0;
    }
}

// K1: histogram of tags
__global__ void k_count(const int* __restrict__ tags) {
    int i = blockIdx.x * blockDim.x + threadIdx.x;
    if (i < NROWS) {
        int t = tags[i] & (NSLOTS - 1);   // defensive mask, slots are pow2
        atomicAdd(&g_counts[t], 1);
    }
}

// K2: exclusive prefix scan over 16384 counts, single block of 512 threads.
// Each thread owns 32 consecutive slots.
__global__ void k_scan() {
    __shared__ int s_sum[512];
    const int PER = NSLOTS / 512;   // 32
    int t = threadIdx.x;
    int base = t * PER;

    int local[PER];
    int run = 0;
#pragma unroll
    for (int j = 0; j < PER; j++) {
        local[j] = run;
        run += g_counts[base + j];
    }
    s_sum[t] = run;
    __syncthreads();

    // Hillis-Steele inclusive scan over 512 thread totals
    for (int d = 1; d < 512; d <<= 1) {
        int v = (t >= d) ? s_sum[t - d] : 0;
        __syncthreads();
        s_sum[t] += v;
        __syncthreads();
    }
    int prefix = (t == 0) ? 0 : s_sum[t - 1];

#pragma unroll
    for (int j = 0; j < PER; j++) {
        g_offsets[base + j] = prefix + local[j];
    }
}

// K3: scatter row indices into per-slot buckets
__global__ void k_scatter(const int* __restrict__ tags) {
    int i = blockIdx.x * blockDim.x + threadIdx.x;
    if (i < NROWS) {
        int t = tags[i] & (NSLOTS - 1);
        int p = atomicAdd(&g_cursor[t], 1);
        g_rows[g_offsets[t] + p] = i;
    }
}

// K4: reduce. One block per output slot; 256 threads x float4 = 1024 floats.
__global__ __launch_bounds__(256) void k_reduce(const float* __restrict__ in,
                                                float* __restrict__ out) {
    int slot = blockIdx.x;
    int t = threadIdx.x;

    int off = g_offsets[slot];
    int cnt = g_counts[slot];

    float4 acc = make_float4(0.f, 0.f, 0.f, 0.f);

    int r = 0;
    // process pairs of rows for MLP
    for (; r + 1 < cnt; r += 2) {
        int row0 = g_rows[off + r];
        int row1 = g_rows[off + r + 1];
        const float4* p0 = (const float4*)(in + (size_t)row0 * DDIM);
        const float4* p1 = (const float4*)(in + (size_t)row1 * DDIM);
        float4 v0 = __ldg(p0 + t);
        float4 v1 = __ldg(p1 + t);
        acc.x += v0.x + v1.x;
        acc.y += v0.y + v1.y;
        acc.z += v0.z + v1.z;
        acc.w += v0.w + v1.w;
    }
    if (r < cnt) {
        int row = g_rows[off + r];
        const float4* p = (const float4*)(in + (size_t)row * DDIM);
        float4 v = __ldg(p + t);
        acc.x += v.x;
        acc.y += v.y;
        acc.z += v.z;
        acc.w += v.w;
    }

    ((float4*)(out + (size_t)slot * DDIM))[t] = acc;
}

// ---------------------------------------------------------------------------
extern "C" void kernel_launch(void* const* d_in, const int* in_sizes, int n_in,
                              void* d_out, int out_size) {
    const float* data = (const float*)d_in[0];
    const int*   tags = (const int*)d_in[1];
    float*       out  = (float*)d_out;

    k_init<<<(NSLOTS + 511) / 512, 512>>>();
    k_count<<<(NROWS + 511) / 512, 512>>>(tags);
    k_scan<<<1, 512>>>();
    k_scatter<<<(NROWS + 511) / 512, 512>>>(tags);
    k_reduce<<<NSLOTS, 256>>>(data, out);
}